// round 16
// baseline (speedup 1.0000x reference)
#include <cuda_runtime.h>
#include <cuda_fp16.h>
#include <mma.h>
using namespace nvcuda;

#define N_NODES 50000
#define N_PAD   50048          // multiple of 128
#define N_EDGES 400000
#define NSCAN_BLK ((N_NODES + 1023) / 1024)   // 49

// ---------------- device scratch (no allocations allowed) ----------------
__device__ __half g_hA[(size_t)N_PAD * 512];     // GEMM input / agg output
__device__ __half g_hB[(size_t)N_PAD * 512];     // GEMM output (half)
__device__ float  g_el[N_NODES * 8];
__device__ float  g_er[N_NODES * 8];
__device__ __half g_hW1[256 * 512];
__device__ __half g_hW2[512 * 512];
__device__ __half g_hW3[512 * 128];
__device__ int    g_rowptr[N_NODES + 1];
__device__ int    g_cursor[N_NODES];
__device__ int    g_eadj[N_EDGES];
__device__ int    g_bsum[NSCAN_BLK];
__device__ int    g_boff[NSCAN_BLK + 1];

__device__ __forceinline__ float lrelu(float x) { return x > 0.f ? x : 0.2f * x; }

// ---------------- CSR build (parallel scan) ----------------
__global__ void count_kernel(const int* __restrict__ dst) {
    int e = blockIdx.x * blockDim.x + threadIdx.x;
    if (e < N_EDGES) atomicAdd(&g_cursor[dst[e]], 1);
}

__global__ void scan_local_kernel() {
    __shared__ int sh[1024];
    int i = blockIdx.x * 1024 + threadIdx.x;
    int v = (i < N_NODES) ? g_cursor[i] : 0;
    sh[threadIdx.x] = v;
    __syncthreads();
    #pragma unroll
    for (int off = 1; off < 1024; off <<= 1) {
        int t = (threadIdx.x >= off) ? sh[threadIdx.x - off] : 0;
        __syncthreads();
        sh[threadIdx.x] += t;
        __syncthreads();
    }
    if (i < N_NODES) g_rowptr[i] = sh[threadIdx.x] - v;
    if (threadIdx.x == 1023) g_bsum[blockIdx.x] = sh[1023];
}

__global__ void scan_bsum_kernel() {
    __shared__ int sh[64];
    int v = (threadIdx.x < NSCAN_BLK) ? g_bsum[threadIdx.x] : 0;
    sh[threadIdx.x] = v;
    __syncthreads();
    #pragma unroll
    for (int off = 1; off < 64; off <<= 1) {
        int t = (threadIdx.x >= off) ? sh[threadIdx.x - off] : 0;
        __syncthreads();
        sh[threadIdx.x] += t;
        __syncthreads();
    }
    if (threadIdx.x < NSCAN_BLK) g_boff[threadIdx.x] = sh[threadIdx.x] - v;
    if (threadIdx.x == 63) g_boff[NSCAN_BLK] = sh[63];
}

__global__ void scan_final_kernel() {
    int i = blockIdx.x * 1024 + threadIdx.x;
    if (i < N_NODES) {
        int r = g_rowptr[i] + g_boff[blockIdx.x];
        g_rowptr[i] = r;
        g_cursor[i] = r;
    }
    if (i == 0) g_rowptr[N_NODES] = g_boff[NSCAN_BLK];
}

__global__ void scatter_kernel(const int* __restrict__ src, const int* __restrict__ dst) {
    int e = blockIdx.x * blockDim.x + threadIdx.x;
    if (e < N_EDGES) {
        int p = atomicAdd(&g_cursor[dst[e]], 1);
        g_eadj[p] = src[e];
    }
}

// ---------------- half conversion helpers ----------------
__global__ void tohalf_kernel(const float* __restrict__ in, __half* __restrict__ out, int count) {
    int i = blockIdx.x * blockDim.x + threadIdx.x;
    if (i < count) out[i] = __float2half_rn(in[i]);
}

__global__ void padW3_kernel(const float* __restrict__ W3) {
    int i = blockIdx.x * blockDim.x + threadIdx.x;
    if (i < 512 * 128) {
        int r = i >> 7, c = i & 127;
        g_hW3[i] = (c < 40) ? __float2half_rn(W3[r * 40 + c]) : __float2half_rn(0.f);
    }
}

// ---------------- cp.async helpers ----------------
__device__ __forceinline__ void cp16(void* smem_dst, const void* gmem_src) {
    unsigned s = (unsigned)__cvta_generic_to_shared(smem_dst);
    asm volatile("cp.async.cg.shared.global [%0], [%1], 16;\n" :: "r"(s), "l"(gmem_src));
}
__device__ __forceinline__ void cp_commit() {
    asm volatile("cp.async.commit_group;\n");
}
template <int N>
__device__ __forceinline__ void cp_wait() {
    asm volatile("cp.async.wait_group %0;\n" :: "n"(N));
}

// ---------------- fp16 WMMA GEMM + fused el/er epilogue ----------------
// HPB heads per 128-col block tile; DREAL real cols per head; HTOT total heads.
#define LDA_H 40    // halves per A row (32 + 8 pad)
#define LDB_H 136   // halves per B row (128 + 8 pad)
#define LDC_H 136   // epilogue tile stride in smem
#define A_STG (128 * LDA_H)
#define B_STG (32 * LDB_H)
#define SMEM_BYTES ((2 * A_STG + 2 * B_STG) * (int)sizeof(__half))

template <int HPB, int DREAL, int HTOT>
__global__ __launch_bounds__(512, 2)
void hgemm_kernel(const __half* __restrict__ A, const __half* __restrict__ B,
                  __half* __restrict__ C, int K, int M,
                  const float* __restrict__ al, const float* __restrict__ ar) {
    extern __shared__ __half smemh[];
    __half* AsBase = smemh;
    __half* BsBase = smemh + 2 * A_STG;

    const int t = threadIdx.x;
    const int wid = t >> 5;
    const int wr = wid & 3;
    const int wc = wid >> 2;
    const int rowBase = blockIdx.y * 128;
    const int colBase = blockIdx.x * 128;

    wmma::fragment<wmma::accumulator, 16, 16, 16, float> c[2][2];
    #pragma unroll
    for (int i = 0; i < 2; i++)
        #pragma unroll
        for (int j = 0; j < 2; j++) wmma::fill_fragment(c[i][j], 0.f);

    auto load_tiles = [&](int st, int k0) {
        __half* As = AsBase + st * A_STG;
        __half* Bs = BsBase + st * B_STG;
        {
            int row = t >> 2, c8 = t & 3;
            cp16(As + row * LDA_H + 8 * c8,
                 A + (size_t)(rowBase + row) * K + k0 + 8 * c8);
        }
        {
            int row = t >> 4, c8 = t & 15;
            cp16(Bs + row * LDB_H + 8 * c8,
                 B + (size_t)(k0 + row) * M + colBase + 8 * c8);
        }
        cp_commit();
    };

    const int KT = K / 32;
    load_tiles(0, 0);

    for (int kt = 0; kt < KT; kt++) {
        if (kt + 1 < KT) { load_tiles((kt + 1) & 1, (kt + 1) * 32); cp_wait<1>(); }
        else             { cp_wait<0>(); }
        __syncthreads();

        const __half* As = AsBase + (kt & 1) * A_STG;
        const __half* Bs = BsBase + (kt & 1) * B_STG;
        #pragma unroll
        for (int kk = 0; kk < 32; kk += 16) {
            wmma::fragment<wmma::matrix_a, 16, 16, 16, __half, wmma::row_major> a[2];
            wmma::fragment<wmma::matrix_b, 16, 16, 16, __half, wmma::row_major> b[2];
            #pragma unroll
            for (int i = 0; i < 2; i++)
                wmma::load_matrix_sync(a[i], As + (wr * 32 + 16 * i) * LDA_H + kk, LDA_H);
            #pragma unroll
            for (int j = 0; j < 2; j++)
                wmma::load_matrix_sync(b[j], Bs + kk * LDB_H + wc * 32 + 16 * j, LDB_H);
            #pragma unroll
            for (int i = 0; i < 2; i++)
                #pragma unroll
                for (int j = 0; j < 2; j++)
                    wmma::mma_sync(c[i][j], a[i], b[j], c[i][j]);
        }
        __syncthreads();
    }

    // epilogue: convert to half; store to global AND to smem tile for score dots
    __half* Cs = smemh;   // 128 x LDC_H halves = 34.8KB <= SMEM_BYTES
    #pragma unroll
    for (int i = 0; i < 2; i++)
        #pragma unroll
        for (int j = 0; j < 2; j++) {
            wmma::fragment<wmma::accumulator, 16, 16, 16, __half> hc;
            #pragma unroll
            for (int x = 0; x < hc.num_elements; x++)
                hc.x[x] = __float2half_rn(c[i][j].x[x]);
            wmma::store_matrix_sync(
                C + (size_t)(rowBase + wr * 32 + 16 * i) * M + colBase + wc * 32 + 16 * j,
                hc, M, wmma::mem_row_major);
            wmma::store_matrix_sync(
                Cs + (wr * 32 + 16 * i) * LDC_H + wc * 32 + 16 * j,
                hc, LDC_H, wmma::mem_row_major);
        }
    __syncthreads();

    // fused scores: one thread per (row, head, el/er)
    constexpr int DPAD = 128 / HPB;
    constexpr int NDOTS = 128 * HPB * 2;        // 512 (HPB=2) or 256 (HPB=1)
    if (t < NDOTS) {
        int r   = t / (HPB * 2);
        int rem = t - r * (HPB * 2);
        int hh  = rem >> 1;
        int sel = rem & 1;
        int row = rowBase + r;
        if (row < N_NODES) {
            int hg = colBase / DPAD + hh;       // global head index
            const float* vec = (sel ? ar : al) + hg * DREAL;
            const __half* crow = Cs + r * LDC_H + hh * DPAD;
            float s = 0.f;
            #pragma unroll
            for (int d2 = 0; d2 < DREAL / 2; d2++) {
                float2 v = __half22float2(*reinterpret_cast<const __half2*>(crow + 2 * d2));
                float2 w = *reinterpret_cast<const float2*>(vec + 2 * d2);
                s = fmaf(v.x, w.x, s);
                s = fmaf(v.y, w.y, s);
            }
            if (sel) g_er[row * HTOT + hg] = s;
            else     g_el[row * HTOT + hg] = s;
        }
    }
}

// ---------------- combined-head fused softmax+agg: warp per node, half gather ----------------
__global__ void agg8_kernel(const __half* __restrict__ feat, __half* __restrict__ out) {
    int n = (blockIdx.x * blockDim.x + threadIdx.x) >> 5;
    int lane = threadIdx.x & 31;
    if (n >= N_NODES) return;
    int beg = g_rowptr[n], end = g_rowptr[n + 1];
    const int hl = lane & 7;
    float er_h = g_er[n * 8 + hl];

    // pass 1: denom per head (4 edges x 8 heads per iteration)
    float part = 0.f;
    for (int j0 = beg; j0 < end; j0 += 4) {
        int jj = j0 + (lane >> 3);
        if (jj < end) {
            int s = g_eadj[jj];
            part += __expf(lrelu(g_el[s * 8 + hl] + er_h));
        }
    }
    part += __shfl_xor_sync(0xffffffffu, part, 8);
    part += __shfl_xor_sync(0xffffffffu, part, 16);
    float inv = (part > 0.f) ? 1.f / part : 0.f;

    // pass 2: weighted half gather, 16B per lane per chunk, 2 chunks
    const int hsel = lane >> 3;      // head-within-chunk (0..3)
    float4 accA[2], accB[2];
    #pragma unroll
    for (int c = 0; c < 2; c++) {
        accA[c] = make_float4(0.f, 0.f, 0.f, 0.f);
        accB[c] = make_float4(0.f, 0.f, 0.f, 0.f);
    }

    for (int j = beg; j < end; ++j) {
        int s = g_eadj[j];
        float xa = 0.f;
        if (lane < 8) xa = __expf(lrelu(g_el[s * 8 + lane] + er_h)) * inv;
        const __half* f = feat + (size_t)s * 512;
        #pragma unroll
        for (int c = 0; c < 2; c++) {
            float a = __shfl_sync(0xffffffffu, xa, 4 * c + hsel);
            float4 raw = *reinterpret_cast<const float4*>(f + c * 256 + 8 * lane);
            const __half2* hp = reinterpret_cast<const __half2*>(&raw);
            float2 v0 = __half22float2(hp[0]);
            float2 v1 = __half22float2(hp[1]);
            float2 v2 = __half22float2(hp[2]);
            float2 v3 = __half22float2(hp[3]);
            accA[c].x = fmaf(a, v0.x, accA[c].x); accA[c].y = fmaf(a, v0.y, accA[c].y);
            accA[c].z = fmaf(a, v1.x, accA[c].z); accA[c].w = fmaf(a, v1.y, accA[c].w);
            accB[c].x = fmaf(a, v2.x, accB[c].x); accB[c].y = fmaf(a, v2.y, accB[c].y);
            accB[c].z = fmaf(a, v3.x, accB[c].z); accB[c].w = fmaf(a, v3.y, accB[c].w);
        }
    }
    __half* orow = out + (size_t)n * 512;
    #pragma unroll
    for (int c = 0; c < 2; c++) {
        __half2 h0 = __floats2half2_rn(accA[c].x, accA[c].y);
        __half2 h1 = __floats2half2_rn(accA[c].z, accA[c].w);
        __half2 h2 = __floats2half2_rn(accB[c].x, accB[c].y);
        __half2 h3 = __floats2half2_rn(accB[c].z, accB[c].w);
        __half2* o2 = reinterpret_cast<__half2*>(orow + c * 256 + 8 * lane);
        o2[0] = h0; o2[1] = h1; o2[2] = h2; o2[3] = h3;
    }
}

// ---------------- per-head fused agg (layer 3, H=1, D=40; half in, fp32 out) ----------------
template <int H, int D>
__global__ void agg_kernel(const __half* __restrict__ feat,
                           float* __restrict__ out, int ldf, int ostride) {
    static_assert(D <= 64, "one half2 per lane");
    int n = (blockIdx.x * blockDim.x + threadIdx.x) >> 5;
    int lane = threadIdx.x & 31;
    if (n >= N_NODES) return;
    const int h = blockIdx.y;
    int beg = g_rowptr[n], end = g_rowptr[n + 1];
    float er_h = g_er[n * H + h];

    float part = 0.f;
    for (int j = beg + lane; j < end; j += 32) {
        int s = g_eadj[j];
        part += __expf(lrelu(g_el[s * H + h] + er_h));
    }
    #pragma unroll
    for (int off = 16; off; off >>= 1)
        part += __shfl_xor_sync(0xffffffffu, part, off);
    float inv = (part > 0.f) ? 1.f / part : 0.f;

    int ci = 2 * lane;
    bool ok = (ci < D);
    const __half* fbase = feat + h * D + ci;
    float2 acc = make_float2(0.f, 0.f);
    for (int j = beg; j < end; ++j) {
        int s = g_eadj[j];
        float a = __expf(lrelu(g_el[s * H + h] + er_h)) * inv;
        if (ok) {
            float2 f = __half22float2(*reinterpret_cast<const __half2*>(fbase + (size_t)s * ldf));
            acc.x = fmaf(a, f.x, acc.x);
            acc.y = fmaf(a, f.y, acc.y);
        }
    }
    if (ok)
        *reinterpret_cast<float2*>(out + (size_t)n * ostride + h * D + ci) = acc;
}

// ---------------- launch ----------------
extern "C" void kernel_launch(void* const* d_in, const int* in_sizes, int n_in,
                              void* d_out, int out_size) {
    const float* features = (const float*)d_in[0];
    const int*   src      = (const int*)d_in[1];
    const int*   dst      = (const int*)d_in[2];
    const float* W1  = (const float*)d_in[3];
    const float* al1 = (const float*)d_in[4];
    const float* ar1 = (const float*)d_in[5];
    const float* W2  = (const float*)d_in[6];
    const float* al2 = (const float*)d_in[7];
    const float* ar2 = (const float*)d_in[8];
    const float* W3  = (const float*)d_in[9];
    const float* al3 = (const float*)d_in[10];
    const float* ar3 = (const float*)d_in[11];
    float* out = (float*)d_out;

    __half *hA, *hB, *hW1, *hW2, *hW3; int* cur;
    cudaGetSymbolAddress((void**)&hA,  g_hA);
    cudaGetSymbolAddress((void**)&hB,  g_hB);
    cudaGetSymbolAddress((void**)&hW1, g_hW1);
    cudaGetSymbolAddress((void**)&hW2, g_hW2);
    cudaGetSymbolAddress((void**)&hW3, g_hW3);
    cudaGetSymbolAddress((void**)&cur, g_cursor);

    cudaFuncSetAttribute(hgemm_kernel<2, 64, 8>,
                         cudaFuncAttributeMaxDynamicSharedMemorySize, SMEM_BYTES);
    cudaFuncSetAttribute(hgemm_kernel<1, 40, 1>,
                         cudaFuncAttributeMaxDynamicSharedMemorySize, SMEM_BYTES);

    const int EB  = (N_EDGES + 255) / 256;
    const int NWB = (N_NODES * 32 + 255) / 256;   // warp per node

    // ---- CSR build (parallel scan) ----
    cudaMemsetAsync(cur, 0, N_NODES * sizeof(int));
    count_kernel<<<EB, 256>>>(dst);
    scan_local_kernel<<<NSCAN_BLK, 1024>>>();
    scan_bsum_kernel<<<1, 64>>>();
    scan_final_kernel<<<NSCAN_BLK, 1024>>>();
    scatter_kernel<<<EB, 256>>>(src, dst);

    // ---- half conversion of GEMM operands ----
    tohalf_kernel<<<(N_NODES * 256 + 255) / 256, 256>>>(features, hA, N_NODES * 256);
    tohalf_kernel<<<(256 * 512 + 255) / 256, 256>>>(W1, hW1, 256 * 512);
    tohalf_kernel<<<(512 * 512 + 255) / 256, 256>>>(W2, hW2, 512 * 512);
    padW3_kernel<<<(512 * 128 + 255) / 256, 256>>>(W3);

    // ---- layer 1: 256 -> 8x64 (GEMM + fused scores) ----
    hgemm_kernel<2, 64, 8><<<dim3(4, N_PAD / 128), 512, SMEM_BYTES>>>(
        hA, hW1, hB, 256, 512, al1, ar1);
    agg8_kernel<<<NWB, 256>>>(hB, hA);

    // ---- layer 2: 8x64 -> 8x64 ----
    hgemm_kernel<2, 64, 8><<<dim3(4, N_PAD / 128), 512, SMEM_BYTES>>>(
        hA, hW2, hB, 512, 512, al2, ar2);
    agg8_kernel<<<NWB, 256>>>(hB, hA);

    // ---- layer 3: 8x64 -> 40 (padded to 128 cols) ----
    hgemm_kernel<1, 40, 1><<<dim3(1, N_PAD / 128), 512, SMEM_BYTES>>>(
        hA, hW3, hB, 512, 128, al3, ar3);
    agg_kernel<1, 40><<<dim3(NWB, 1), 256>>>(hB, out, 128, 40);
}

// round 17
// speedup vs baseline: 1.4464x; 1.4464x over previous
#include <cuda_runtime.h>
#include <cuda_fp16.h>
#include <mma.h>
using namespace nvcuda;

#define N_NODES 50000
#define N_PAD   50048          // multiple of 128
#define N_EDGES 400000
#define NSCAN_BLK ((N_NODES + 1023) / 1024)   // 49

// ---------------- device scratch (no allocations allowed) ----------------
__device__ __half g_hA[(size_t)N_PAD * 512];     // GEMM input / agg output
__device__ __half g_hB[(size_t)N_PAD * 512];     // GEMM output (half)
__device__ float  g_el[N_NODES * 8];
__device__ float  g_er[N_NODES * 8];
__device__ __half g_hW1[256 * 512];
__device__ __half g_hW2[512 * 512];
__device__ __half g_hW3[512 * 128];
__device__ int    g_rowptr[N_NODES + 1];
__device__ int    g_cursor[N_NODES];
__device__ int    g_eadj[N_EDGES];
__device__ int    g_bsum[NSCAN_BLK];
__device__ int    g_boff[NSCAN_BLK + 1];

__device__ __forceinline__ float lrelu(float x) { return x > 0.f ? x : 0.2f * x; }

// ---------------- CSR build (parallel scan) ----------------
__global__ void count_kernel(const int* __restrict__ dst) {
    int e = blockIdx.x * blockDim.x + threadIdx.x;
    if (e < N_EDGES) atomicAdd(&g_cursor[dst[e]], 1);
}

__global__ void scan_local_kernel() {
    __shared__ int sh[1024];
    int i = blockIdx.x * 1024 + threadIdx.x;
    int v = (i < N_NODES) ? g_cursor[i] : 0;
    sh[threadIdx.x] = v;
    __syncthreads();
    #pragma unroll
    for (int off = 1; off < 1024; off <<= 1) {
        int t = (threadIdx.x >= off) ? sh[threadIdx.x - off] : 0;
        __syncthreads();
        sh[threadIdx.x] += t;
        __syncthreads();
    }
    if (i < N_NODES) g_rowptr[i] = sh[threadIdx.x] - v;
    if (threadIdx.x == 1023) g_bsum[blockIdx.x] = sh[1023];
}

__global__ void scan_bsum_kernel() {
    __shared__ int sh[64];
    int v = (threadIdx.x < NSCAN_BLK) ? g_bsum[threadIdx.x] : 0;
    sh[threadIdx.x] = v;
    __syncthreads();
    #pragma unroll
    for (int off = 1; off < 64; off <<= 1) {
        int t = (threadIdx.x >= off) ? sh[threadIdx.x - off] : 0;
        __syncthreads();
        sh[threadIdx.x] += t;
        __syncthreads();
    }
    if (threadIdx.x < NSCAN_BLK) g_boff[threadIdx.x] = sh[threadIdx.x] - v;
    if (threadIdx.x == 63) g_boff[NSCAN_BLK] = sh[63];
}

__global__ void scan_final_kernel() {
    int i = blockIdx.x * 1024 + threadIdx.x;
    if (i < N_NODES) {
        int r = g_rowptr[i] + g_boff[blockIdx.x];
        g_rowptr[i] = r;
        g_cursor[i] = r;
    }
    if (i == 0) g_rowptr[N_NODES] = g_boff[NSCAN_BLK];
}

__global__ void scatter_kernel(const int* __restrict__ src, const int* __restrict__ dst) {
    int e = blockIdx.x * blockDim.x + threadIdx.x;
    if (e < N_EDGES) {
        int p = atomicAdd(&g_cursor[dst[e]], 1);
        g_eadj[p] = src[e];
    }
}

// ---------------- merged half conversion: features + W1 + W2 in one launch ----------------
#define CVT_FEAT (N_NODES * 256)
#define CVT_W1   (256 * 512)
#define CVT_W2   (512 * 512)
#define CVT_TOTAL (CVT_FEAT + CVT_W1 + CVT_W2)

__global__ void convert_all_kernel(const float* __restrict__ feat,
                                   const float* __restrict__ W1,
                                   const float* __restrict__ W2) {
    int i = blockIdx.x * blockDim.x + threadIdx.x;
    if (i < CVT_FEAT) {
        g_hA[i] = __float2half_rn(feat[i]);
    } else if (i < CVT_FEAT + CVT_W1) {
        int k = i - CVT_FEAT;
        g_hW1[k] = __float2half_rn(W1[k]);
    } else if (i < CVT_TOTAL) {
        int k = i - CVT_FEAT - CVT_W1;
        g_hW2[k] = __float2half_rn(W2[k]);
    }
}

__global__ void padW3_kernel(const float* __restrict__ W3) {
    int i = blockIdx.x * blockDim.x + threadIdx.x;
    if (i < 512 * 128) {
        int r = i >> 7, c = i & 127;
        g_hW3[i] = (c < 40) ? __float2half_rn(W3[r * 40 + c]) : __float2half_rn(0.f);
    }
}

// ---------------- cp.async helpers ----------------
__device__ __forceinline__ void cp16(void* smem_dst, const void* gmem_src) {
    unsigned s = (unsigned)__cvta_generic_to_shared(smem_dst);
    asm volatile("cp.async.cg.shared.global [%0], [%1], 16;\n" :: "r"(s), "l"(gmem_src));
}
__device__ __forceinline__ void cp_commit() {
    asm volatile("cp.async.commit_group;\n");
}
template <int N>
__device__ __forceinline__ void cp_wait() {
    asm volatile("cp.async.wait_group %0;\n" :: "n"(N));
}

// ---------------- fp16 WMMA GEMM (fp32 accumulate, half output) ----------------
#define LDA_H 40    // halves per A row (32 + 8 pad)
#define LDB_H 136   // halves per B row (128 + 8 pad)
#define A_STG (128 * LDA_H)
#define B_STG (32 * LDB_H)
#define SMEM_BYTES ((2 * A_STG + 2 * B_STG) * (int)sizeof(__half))

__global__ __launch_bounds__(512, 2)
void hgemm_kernel(const __half* __restrict__ A, const __half* __restrict__ B,
                  __half* __restrict__ C, int K, int M) {
    extern __shared__ __half smemh[];
    __half* AsBase = smemh;
    __half* BsBase = smemh + 2 * A_STG;

    const int t = threadIdx.x;
    const int wid = t >> 5;
    const int wr = wid & 3;
    const int wc = wid >> 2;
    const int rowBase = blockIdx.y * 128;
    const int colBase = blockIdx.x * 128;

    wmma::fragment<wmma::accumulator, 16, 16, 16, float> c[2][2];
    #pragma unroll
    for (int i = 0; i < 2; i++)
        #pragma unroll
        for (int j = 0; j < 2; j++) wmma::fill_fragment(c[i][j], 0.f);

    auto load_tiles = [&](int st, int k0) {
        __half* As = AsBase + st * A_STG;
        __half* Bs = BsBase + st * B_STG;
        {
            int row = t >> 2, c8 = t & 3;
            cp16(As + row * LDA_H + 8 * c8,
                 A + (size_t)(rowBase + row) * K + k0 + 8 * c8);
        }
        {
            int row = t >> 4, c8 = t & 15;
            cp16(Bs + row * LDB_H + 8 * c8,
                 B + (size_t)(k0 + row) * M + colBase + 8 * c8);
        }
        cp_commit();
    };

    const int KT = K / 32;
    load_tiles(0, 0);

    for (int kt = 0; kt < KT; kt++) {
        if (kt + 1 < KT) { load_tiles((kt + 1) & 1, (kt + 1) * 32); cp_wait<1>(); }
        else             { cp_wait<0>(); }
        __syncthreads();

        const __half* As = AsBase + (kt & 1) * A_STG;
        const __half* Bs = BsBase + (kt & 1) * B_STG;
        #pragma unroll
        for (int kk = 0; kk < 32; kk += 16) {
            wmma::fragment<wmma::matrix_a, 16, 16, 16, __half, wmma::row_major> a[2];
            wmma::fragment<wmma::matrix_b, 16, 16, 16, __half, wmma::row_major> b[2];
            #pragma unroll
            for (int i = 0; i < 2; i++)
                wmma::load_matrix_sync(a[i], As + (wr * 32 + 16 * i) * LDA_H + kk, LDA_H);
            #pragma unroll
            for (int j = 0; j < 2; j++)
                wmma::load_matrix_sync(b[j], Bs + kk * LDB_H + wc * 32 + 16 * j, LDB_H);
            #pragma unroll
            for (int i = 0; i < 2; i++)
                #pragma unroll
                for (int j = 0; j < 2; j++)
                    wmma::mma_sync(c[i][j], a[i], b[j], c[i][j]);
        }
        __syncthreads();
    }

    // half epilogue: fp32 frag -> fp16 frag elementwise (layouts match for m16n16k16)
    #pragma unroll
    for (int i = 0; i < 2; i++)
        #pragma unroll
        for (int j = 0; j < 2; j++) {
            wmma::fragment<wmma::accumulator, 16, 16, 16, __half> hc;
            #pragma unroll
            for (int x = 0; x < hc.num_elements; x++)
                hc.x[x] = __float2half_rn(c[i][j].x[x]);
            wmma::store_matrix_sync(
                C + (size_t)(rowBase + wr * 32 + 16 * i) * M + colBase + wc * 32 + 16 * j,
                hc, M, wmma::mem_row_major);
        }
}

// ---------------- per-node attention scores el/er (half feat) ----------------
template <int H, int D>
__global__ void scores_kernel(const __half* __restrict__ feat,
                              const float* __restrict__ al,
                              const float* __restrict__ ar, int ldf) {
    static_assert(D <= 64, "one half2 per lane");
    int g = (blockIdx.x * blockDim.x + threadIdx.x) >> 5;
    int lane = threadIdx.x & 31;
    if (g >= N_NODES * H) return;
    int n = g / H, h = g % H;
    int ci = 2 * lane;
    float sl = 0.f, sr = 0.f;
    if (ci < D) {
        __half2 v2 = *reinterpret_cast<const __half2*>(feat + (size_t)n * ldf + h * D + ci);
        float2 v = __half22float2(v2);
        float2 a = *reinterpret_cast<const float2*>(al + h * D + ci);
        float2 b = *reinterpret_cast<const float2*>(ar + h * D + ci);
        sl = v.x * a.x + v.y * a.y;
        sr = v.x * b.x + v.y * b.y;
    }
    #pragma unroll
    for (int off = 16; off; off >>= 1) {
        sl += __shfl_down_sync(0xffffffffu, sl, off);
        sr += __shfl_down_sync(0xffffffffu, sr, off);
    }
    if (lane == 0) { g_el[n * H + h] = sl; g_er[n * H + h] = sr; }
}

// ---------------- combined-head fused softmax+agg: warp per node, half gather ----------------
__global__ void agg8_kernel(const __half* __restrict__ feat, __half* __restrict__ out) {
    int n = (blockIdx.x * blockDim.x + threadIdx.x) >> 5;
    int lane = threadIdx.x & 31;
    if (n >= N_NODES) return;
    int beg = g_rowptr[n], end = g_rowptr[n + 1];
    const int hl = lane & 7;
    float er_h = g_er[n * 8 + hl];

    // pass 1: denom per head (4 edges x 8 heads per iteration)
    float part = 0.f;
    for (int j0 = beg; j0 < end; j0 += 4) {
        int jj = j0 + (lane >> 3);
        if (jj < end) {
            int s = g_eadj[jj];
            part += __expf(lrelu(g_el[s * 8 + hl] + er_h));
        }
    }
    part += __shfl_xor_sync(0xffffffffu, part, 8);
    part += __shfl_xor_sync(0xffffffffu, part, 16);
    float inv = (part > 0.f) ? 1.f / part : 0.f;

    // pass 2: weighted half gather, 16B per lane per chunk, 2 chunks
    const int hsel = lane >> 3;      // head-within-chunk (0..3)
    float4 accA[2], accB[2];
    #pragma unroll
    for (int c = 0; c < 2; c++) {
        accA[c] = make_float4(0.f, 0.f, 0.f, 0.f);
        accB[c] = make_float4(0.f, 0.f, 0.f, 0.f);
    }

    for (int j = beg; j < end; ++j) {
        int s = g_eadj[j];
        float xa = 0.f;
        if (lane < 8) xa = __expf(lrelu(g_el[s * 8 + lane] + er_h)) * inv;
        const __half* f = feat + (size_t)s * 512;
        #pragma unroll
        for (int c = 0; c < 2; c++) {
            float a = __shfl_sync(0xffffffffu, xa, 4 * c + hsel);
            float4 raw = *reinterpret_cast<const float4*>(f + c * 256 + 8 * lane);
            const __half2* hp = reinterpret_cast<const __half2*>(&raw);
            float2 v0 = __half22float2(hp[0]);
            float2 v1 = __half22float2(hp[1]);
            float2 v2 = __half22float2(hp[2]);
            float2 v3 = __half22float2(hp[3]);
            accA[c].x = fmaf(a, v0.x, accA[c].x); accA[c].y = fmaf(a, v0.y, accA[c].y);
            accA[c].z = fmaf(a, v1.x, accA[c].z); accA[c].w = fmaf(a, v1.y, accA[c].w);
            accB[c].x = fmaf(a, v2.x, accB[c].x); accB[c].y = fmaf(a, v2.y, accB[c].y);
            accB[c].z = fmaf(a, v3.x, accB[c].z); accB[c].w = fmaf(a, v3.y, accB[c].w);
        }
    }
    __half* orow = out + (size_t)n * 512;
    #pragma unroll
    for (int c = 0; c < 2; c++) {
        __half2 h0 = __floats2half2_rn(accA[c].x, accA[c].y);
        __half2 h1 = __floats2half2_rn(accA[c].z, accA[c].w);
        __half2 h2 = __floats2half2_rn(accB[c].x, accB[c].y);
        __half2 h3 = __floats2half2_rn(accB[c].z, accB[c].w);
        __half2* o2 = reinterpret_cast<__half2*>(orow + c * 256 + 8 * lane);
        o2[0] = h0; o2[1] = h1; o2[2] = h2; o2[3] = h3;
    }
}

// ---------------- per-head fused agg (layer 3, H=1, D=40; half in, fp32 out) ----------------
template <int H, int D>
__global__ void agg_kernel(const __half* __restrict__ feat,
                           float* __restrict__ out, int ldf, int ostride) {
    static_assert(D <= 64, "one half2 per lane");
    int n = (blockIdx.x * blockDim.x + threadIdx.x) >> 5;
    int lane = threadIdx.x & 31;
    if (n >= N_NODES) return;
    const int h = blockIdx.y;
    int beg = g_rowptr[n], end = g_rowptr[n + 1];
    float er_h = g_er[n * H + h];

    float part = 0.f;
    for (int j = beg + lane; j < end; j += 32) {
        int s = g_eadj[j];
        part += __expf(lrelu(g_el[s * H + h] + er_h));
    }
    #pragma unroll
    for (int off = 16; off; off >>= 1)
        part += __shfl_xor_sync(0xffffffffu, part, off);
    float inv = (part > 0.f) ? 1.f / part : 0.f;

    int ci = 2 * lane;
    bool ok = (ci < D);
    const __half* fbase = feat + h * D + ci;
    float2 acc = make_float2(0.f, 0.f);
    for (int j = beg; j < end; ++j) {
        int s = g_eadj[j];
        float a = __expf(lrelu(g_el[s * H + h] + er_h)) * inv;
        if (ok) {
            float2 f = __half22float2(*reinterpret_cast<const __half2*>(fbase + (size_t)s * ldf));
            acc.x = fmaf(a, f.x, acc.x);
            acc.y = fmaf(a, f.y, acc.y);
        }
    }
    if (ok)
        *reinterpret_cast<float2*>(out + (size_t)n * ostride + h * D + ci) = acc;
}

// ---------------- launch ----------------
extern "C" void kernel_launch(void* const* d_in, const int* in_sizes, int n_in,
                              void* d_out, int out_size) {
    const float* features = (const float*)d_in[0];
    const int*   src      = (const int*)d_in[1];
    const int*   dst      = (const int*)d_in[2];
    const float* W1  = (const float*)d_in[3];
    const float* al1 = (const float*)d_in[4];
    const float* ar1 = (const float*)d_in[5];
    const float* W2  = (const float*)d_in[6];
    const float* al2 = (const float*)d_in[7];
    const float* ar2 = (const float*)d_in[8];
    const float* W3  = (const float*)d_in[9];
    const float* al3 = (const float*)d_in[10];
    const float* ar3 = (const float*)d_in[11];
    float* out = (float*)d_out;

    __half *hA, *hB, *hW1, *hW2, *hW3; int* cur;
    cudaGetSymbolAddress((void**)&hA,  g_hA);
    cudaGetSymbolAddress((void**)&hB,  g_hB);
    cudaGetSymbolAddress((void**)&hW1, g_hW1);
    cudaGetSymbolAddress((void**)&hW2, g_hW2);
    cudaGetSymbolAddress((void**)&hW3, g_hW3);
    cudaGetSymbolAddress((void**)&cur, g_cursor);

    cudaFuncSetAttribute(hgemm_kernel,
                         cudaFuncAttributeMaxDynamicSharedMemorySize, SMEM_BYTES);

    const int EB  = (N_EDGES + 255) / 256;
    const int NWB = (N_NODES * 32 + 255) / 256;   // warp per node

    // ---- CSR build (parallel scan) ----
    cudaMemsetAsync(cur, 0, N_NODES * sizeof(int));
    count_kernel<<<EB, 256>>>(dst);
    scan_local_kernel<<<NSCAN_BLK, 1024>>>();
    scan_bsum_kernel<<<1, 64>>>();
    scan_final_kernel<<<NSCAN_BLK, 1024>>>();
    scatter_kernel<<<EB, 256>>>(src, dst);

    // ---- half conversion of GEMM operands (merged) ----
    convert_all_kernel<<<(CVT_TOTAL + 255) / 256, 256>>>(features, W1, W2);
    padW3_kernel<<<(512 * 128 + 255) / 256, 256>>>(W3);

    // ---- layer 1: 256 -> 8x64 ----
    hgemm_kernel<<<dim3(4, N_PAD / 128), 512, SMEM_BYTES>>>(hA, hW1, hB, 256, 512);
    scores_kernel<8, 64><<<N_NODES, 256>>>(hB, al1, ar1, 512);
    agg8_kernel<<<NWB, 256>>>(hB, hA);

    // ---- layer 2: 8x64 -> 8x64 ----
    hgemm_kernel<<<dim3(4, N_PAD / 128), 512, SMEM_BYTES>>>(hA, hW2, hB, 512, 512);
    scores_kernel<8, 64><<<N_NODES, 256>>>(hB, al2, ar2, 512);
    agg8_kernel<<<NWB, 256>>>(hB, hA);

    // ---- layer 3: 8x64 -> 40 (padded to 128 cols) ----
    hgemm_kernel<<<dim3(1, N_PAD / 128), 512, SMEM_BYTES>>>(hA, hW3, hB, 512, 128);
    scores_kernel<1, 40><<<(N_NODES + 7) / 8, 256>>>(hB, al3, ar3, 128);
    agg_kernel<1, 40><<<dim3(NWB, 1), 256>>>(hB, out, 128, 40);
}